// round 13
// baseline (speedup 1.0000x reference)
#include <cuda_runtime.h>
#include <math.h>

// Problem constants (fixed shapes)
#define BW_TOTAL 8192   // B*W rows
#define HDIM     512    // hidden
#define VOCAB    128    // A
#define QDIM     256    // Q
#define CLEN     20     // max_char_len
#define MROWS    28     // rows per CTA
#define NTH      512    // 16 warps
#define NCTA     293    // ceil(8192/28)
#define HPAD     36     // padded row stride of transposed h (36*4B = 144B, 16B-aligned)

// ---------------- device scratch (repacked weights) ----------------
// Arithmetic contract (bit-exact vs reference backend): every output element
// is ONE fp32 FMA chain over k ascending from 0. f32x2 packs two ROWS per
// register in Phase A (two vocab in Phase B); each lane is its own chain.
__device__ float4 g_wpkG4[262144];   // w_hh:  [ui:16][k:512][lane:32] -> (i,f,g,o) for unit u=ui*32+lane
__device__ float4 g_wihT4[65536];    // w_ih^T gather: [a:128][u:512] -> (i,f,g,o)
__device__ float4 g_wout4[16384];    // w_out: [k:512][lane:32] -> vocab (4*lane..4*lane+3)
__device__ float4 g_win4T[32768];    // w_in:  [k4:64][u:512] -> w_in[u][4k4..4k4+3]
__device__ float4 g_bsum4[512];      // b_ih+b_hh: [u:512] -> (i,f,g,o)

__global__ void repack_kernel(const float* __restrict__ w_in,
                              const float* __restrict__ w_ih,
                              const float* __restrict__ w_hh,
                              const float* __restrict__ b_ih,
                              const float* __restrict__ b_hh,
                              const float* __restrict__ w_out)
{
    int idx = blockIdx.x * blockDim.x + threadIdx.x;
    int stride = gridDim.x * blockDim.x;
    float* wpk = (float*)g_wpkG4;
    for (int i = idx; i < 1048576; i += stride) {
        int g = i & 3, lane = (i >> 2) & 31, k = (i >> 7) & 511, ui = i >> 16;
        wpk[i] = w_hh[(g * 512 + ui * 32 + lane) * HDIM + k];
    }
    float* wih = (float*)g_wihT4;
    for (int i = idx; i < 262144; i += stride) {
        int g = i & 3, u = (i >> 2) & 511, a = i >> 11;
        wih[i] = w_ih[(g * 512 + u) * VOCAB + a];
    }
    float* wou = (float*)g_wout4;
    for (int i = idx; i < 65536; i += stride) {
        int j = i & 3, lane = (i >> 2) & 31, k = i >> 7;
        wou[i] = w_out[(4 * lane + j) * HDIM + k];
    }
    float* win = (float*)g_win4T;
    for (int i = idx; i < 131072; i += stride) {
        int j = i & 3, u = (i >> 2) & 511, k4 = i >> 11;
        win[i] = w_in[u * QDIM + 4 * k4 + j];
    }
    float* bs = (float*)g_bsum4;
    for (int i = idx; i < 2048; i += stride) {
        int g = i & 3, u = i >> 2;
        bs[i] = __fadd_rn(b_ih[g * 512 + u], b_hh[g * 512 + u]);
    }
}

// ---------------- f32x2 helpers ----------------
typedef unsigned long long ull;

__device__ __forceinline__ void dfma(ull& d, ull a, ull b) {
    asm("fma.rn.f32x2 %0, %1, %2, %0;" : "+l"(d) : "l"(a), "l"(b));
}
__device__ __forceinline__ ull f2u(float x, float y) {
    ull r; asm("mov.b64 %0, {%1, %2};" : "=l"(r) : "f"(x), "f"(y)); return r;
}
__device__ __forceinline__ float2 u2f(ull v) {
    float2 r; asm("mov.b64 {%0, %1}, %2;" : "=f"(r.x), "=f"(r.y) : "l"(v)); return r;
}

// ---------------- XLA elemental tanh / logistic (no contraction) ----------------
__device__ __forceinline__ float fast_tanh(float x) {
    const float kClamp = 7.90531110763549805f;
    float xc = fminf(fmaxf(x, -kClamp), kClamp);
    float x2 = __fmul_rn(xc, xc);
    float p = -2.76076847742355e-16f;
    p = __fadd_rn(__fmul_rn(p, x2), 2.00018790482477e-13f);
    p = __fadd_rn(__fmul_rn(p, x2), -8.60467152213735e-11f);
    p = __fadd_rn(__fmul_rn(p, x2), 5.12229709037114e-08f);
    p = __fadd_rn(__fmul_rn(p, x2), 1.48572235717979e-05f);
    p = __fadd_rn(__fmul_rn(p, x2), 6.37261928875436e-04f);
    p = __fadd_rn(__fmul_rn(p, x2), 4.89352455891786e-03f);
    float np = __fmul_rn(xc, p);
    float q = 1.19825839466702e-06f;
    q = __fadd_rn(__fmul_rn(q, x2), 1.18534705686654e-04f);
    q = __fadd_rn(__fmul_rn(q, x2), 2.26843463243900e-03f);
    q = __fadd_rn(__fmul_rn(q, x2), 4.89352518554385e-03f);
    float r = __fdiv_rn(np, q);
    return (fabsf(x) < 0.0004f) ? x : r;
}
__device__ __forceinline__ float sig_x(float x) {
    float t = fast_tanh(__fmul_rn(0.5f, x));
    return __fadd_rn(__fmul_rn(0.5f, t), 0.5f);
}

// ---------------- Phase A worker: one warp, 32 units (ui), NQ*4 rows ----------------
// hbase = hold + rowbase (rowbase*4 bytes must be 16B-aligned: rowbase in {0,16})
template<int NQ>
__device__ __forceinline__ void phaseA_warp(
    const float* __restrict__ hbase,
    float* __restrict__ hnew,
    float* __restrict__ cs,
    const int* __restrict__ xidx,
    int u, int ui, int rowbase, int lane)
{
    ull acc[2 * NQ][4];
#pragma unroll
    for (int rp = 0; rp < 2 * NQ; ++rp)
#pragma unroll
        for (int g = 0; g < 4; ++g) acc[rp][g] = 0ull;

    const float4* wp = g_wpkG4 + (size_t)ui * 512 * 32 + lane;

#pragma unroll 1
    for (int k4 = 0; k4 < 128; ++k4) {
        const float4* wk = wp + k4 * 128;
        float4 w0 = __ldg(wk), w1 = __ldg(wk + 32),
               w2 = __ldg(wk + 64), w3 = __ldg(wk + 96);
        const float* hk = hbase + (4 * k4) * HPAD;
#define KSTEP(W, KO)                                                           \
        {                                                                      \
            ull bi_ = f2u(W.x, W.x), bf_ = f2u(W.y, W.y);                      \
            ull bg_ = f2u(W.z, W.z), bo_ = f2u(W.w, W.w);                      \
            const float4* hr = (const float4*)(hk + (KO) * HPAD);              \
            _Pragma("unroll")                                                  \
            for (int rq = 0; rq < NQ; ++rq) {                                  \
                float4 hv = hr[rq];                                            \
                ull h01 = f2u(hv.x, hv.y), h23 = f2u(hv.z, hv.w);              \
                dfma(acc[2*rq][0], h01, bi_);                                  \
                dfma(acc[2*rq][1], h01, bf_);                                  \
                dfma(acc[2*rq][2], h01, bg_);                                  \
                dfma(acc[2*rq][3], h01, bo_);                                  \
                dfma(acc[2*rq+1][0], h23, bi_);                                \
                dfma(acc[2*rq+1][1], h23, bf_);                                \
                dfma(acc[2*rq+1][2], h23, bg_);                                \
                dfma(acc[2*rq+1][3], h23, bo_);                                \
            }                                                                  \
        }
        KSTEP(w0, 0) KSTEP(w1, 1) KSTEP(w2, 2) KSTEP(w3, 3)
#undef KSTEP
    }

    // pointwise epilogue for this unit column, rows rowbase .. rowbase+4*NQ-1
    float4 bs = g_bsum4[u];
#pragma unroll
    for (int rp = 0; rp < 2 * NQ; ++rp) {
        float2 vi = u2f(acc[rp][0]);
        float2 vf = u2f(acc[rp][1]);
        float2 vg = u2f(acc[rp][2]);
        float2 vo = u2f(acc[rp][3]);
#pragma unroll
        for (int e = 0; e < 2; ++e) {
            int row = rowbase + 2 * rp + e;
            float di = e ? vi.y : vi.x;
            float df = e ? vf.y : vf.x;
            float dg = e ? vg.y : vg.x;
            float dd = e ? vo.y : vo.x;
            float4 wv = g_wihT4[(size_t)xidx[row] * HDIM + u];
            // reference order: (x-proj + h-proj) + bias
            float gi = __fadd_rn(__fadd_rn(wv.x, di), bs.x);
            float gf = __fadd_rn(__fadd_rn(wv.y, df), bs.y);
            float gg = __fadd_rn(__fadd_rn(wv.z, dg), bs.z);
            float go = __fadd_rn(__fadd_rn(wv.w, dd), bs.w);
            float iv = sig_x(gi);
            float fv = sig_x(gf);
            float gv = fast_tanh(gg);
            float ov = sig_x(go);
            float cv = __fadd_rn(__fmul_rn(fv, cs[row * HDIM + u]),
                                 __fmul_rn(iv, gv));
            cs[row * HDIM + u] = cv;
            hnew[u * HPAD + row] = __fmul_rn(ov, fast_tanh(cv));
        }
    }
}

// ---------------- persistent decoder kernel ----------------
// smem: transposed h ping-pong hT[2][512][HPAD], c [28][512], xidx[28]
#define SMEM_FLOATS (2 * HDIM * HPAD + MROWS * HDIM + 32)
#define SMEM_BYTES  (SMEM_FLOATS * 4)

__global__ void __launch_bounds__(NTH, 1)
decoder_kernel(const float* __restrict__ qr,
               const float* __restrict__ b_in,
               const float* __restrict__ b_out,
               float* __restrict__ out)
{
    extern __shared__ float sm[];
    float* hT0  = sm;                          // [k:512][HPAD]
    float* hT1  = sm + HDIM * HPAD;            // [k:512][HPAD]
    float* cs   = sm + 2 * HDIM * HPAD;        // [row:28][u:512]
    int*   xidx = (int*)(sm + 2 * HDIM * HPAD + MROWS * HDIM);

    const int tid  = threadIdx.x;
    const int lane = tid & 31;
    const int wid  = tid >> 5;                 // 0..15
    const int growbase = blockIdx.x * MROWS;

    // ===== Phase 0a: stage X transposed into cs region: xsT[k:256][HPAD] =====
    float* xsT = cs;
    for (int i = tid; i < MROWS * QDIM; i += NTH) {
        int row = i >> 8, q = i & 255;
        int gr = growbase + row;
        float v = 0.0f;
        if (gr < BW_TOTAL) v = __ldg(qr + (size_t)gr * QDIM + q);
        xsT[q * HPAD + row] = v;
    }
    if (tid < MROWS) xidx[tid] = 0;            // <start>
    __syncthreads();

    // ===== Phase 0b: h0 = X @ w_in^T + b_in (16 warps, ui = wid, all 28 rows) =====
    {
        const int ui = wid;
        const int u  = ui * 32 + lane;
        ull acc[14];
#pragma unroll
        for (int rp = 0; rp < 14; ++rp) acc[rp] = 0ull;
        const float4* wip = g_win4T + u;
#pragma unroll 1
        for (int k4 = 0; k4 < 64; ++k4) {
            float4 w = __ldg(wip + k4 * 512);
#define XSTEP(WS, KO)                                                          \
            {                                                                  \
                ull b_ = f2u(WS, WS);                                          \
                const float4* xr = (const float4*)(xsT + (4 * k4 + (KO)) * HPAD); \
                _Pragma("unroll")                                              \
                for (int rq = 0; rq < 7; ++rq) {                               \
                    float4 xv = xr[rq];                                        \
                    dfma(acc[2 * rq],     f2u(xv.x, xv.y), b_);                \
                    dfma(acc[2 * rq + 1], f2u(xv.z, xv.w), b_);                \
                }                                                              \
            }
            XSTEP(w.x, 0) XSTEP(w.y, 1) XSTEP(w.z, 2) XSTEP(w.w, 3)
#undef XSTEP
        }
        float bi = __ldg(b_in + u);
#pragma unroll
        for (int rp = 0; rp < 14; ++rp) {
            float2 v = u2f(acc[rp]);
            hT0[u * HPAD + 2 * rp]     = __fadd_rn(v.x, bi);
            hT0[u * HPAD + 2 * rp + 1] = __fadd_rn(v.y, bi);
        }
    }
    __syncthreads();
    // zero c (xsT region now dead)
    for (int i = tid; i < MROWS * HDIM; i += NTH) cs[i] = 0.0f;
    __syncthreads();

    float4 bo4 = __ldg(((const float4*)b_out) + lane);   // vocab 4*lane..4*lane+3

    // Phase A warp identity: unit-group + row-half
    const int uig   = wid >> 1;                // 0..7
    const int rhalf = wid & 1;                 // 0: rows 0-15 (NQ=4), 1: rows 16-27 (NQ=3)
    const int rowbase = rhalf ? 16 : 0;

    // ===== main recurrence: 20 steps =====
    for (int t = 0; t < CLEN; ++t) {
        const float* hold = (t & 1) ? hT1 : hT0;
        float*       hnew = (t & 1) ? hT0 : hT1;

        // ---- Phase A: 16 warps = 8 unit-groups x 2 row-halves, 2 unit passes ----
        for (int pass = 0; pass < 2; ++pass) {
            const int ui = 2 * uig + pass;
            const int u  = ui * 32 + lane;
            if (rhalf == 0)
                phaseA_warp<4>(hold + rowbase, hnew, cs, xidx, u, ui, rowbase, lane);
            else
                phaseA_warp<3>(hold + rowbase, hnew, cs, xidx, u, ui, rowbase, lane);
        }
        __syncthreads();

        // ---- Phase B: logits = h_new @ w_out^T + b_out ; 14 warps x 2 rows ----
        if (wid < 14) {
            ull a01[2] = {0ull, 0ull}, a23[2] = {0ull, 0ull};
            const float4* wq = g_wout4 + lane;
            const float* hb = hnew + 2 * wid;
#pragma unroll 1
            for (int u4 = 0; u4 < 128; ++u4) {
                float4 w0 = __ldg(wq + (4 * u4 + 0) * 32);
                float4 w1 = __ldg(wq + (4 * u4 + 1) * 32);
                float4 w2 = __ldg(wq + (4 * u4 + 2) * 32);
                float4 w3 = __ldg(wq + (4 * u4 + 3) * 32);
#define USTEP(W, UO)                                                           \
                {                                                              \
                    float2 hv = *(const float2*)(hb + (4 * u4 + (UO)) * HPAD); \
                    ull wab = f2u(W.x, W.y), wcd = f2u(W.z, W.w);              \
                    dfma(a01[0], f2u(hv.x, hv.x), wab);                        \
                    dfma(a23[0], f2u(hv.x, hv.x), wcd);                        \
                    dfma(a01[1], f2u(hv.y, hv.y), wab);                        \
                    dfma(a23[1], f2u(hv.y, hv.y), wcd);                        \
                }
                USTEP(w0, 0) USTEP(w1, 1) USTEP(w2, 2) USTEP(w3, 3)
#undef USTEP
            }
#pragma unroll
            for (int r = 0; r < 2; ++r) {
                int row = 2 * wid + r;
                int gr = growbase + row;
                float2 v01 = u2f(a01[r]), v23 = u2f(a23[r]);
                float lg0 = __fadd_rn(v01.x, bo4.x);
                float lg1 = __fadd_rn(v01.y, bo4.y);
                float lg2 = __fadd_rn(v23.x, bo4.z);
                float lg3 = __fadd_rn(v23.y, bo4.w);

                if (gr < BW_TOTAL) {
                    float4 o4 = make_float4(lg0, lg1, lg2, lg3);
                    *(float4*)(out + ((size_t)gr * CLEN + t) * VOCAB + 4 * lane) = o4;
                }
                // local argmax (ascending index, first-max tie-break)
                float bv = lg0; int bi = 4 * lane;
                if (lg1 > bv) { bv = lg1; bi = 4 * lane + 1; }
                if (lg2 > bv) { bv = lg2; bi = 4 * lane + 2; }
                if (lg3 > bv) { bv = lg3; bi = 4 * lane + 3; }
#pragma unroll
                for (int off = 16; off; off >>= 1) {
                    float ov = __shfl_xor_sync(0xffffffffu, bv, off);
                    int   oi = __shfl_xor_sync(0xffffffffu, bi, off);
                    if (ov > bv || (ov == bv && oi < bi)) { bv = ov; bi = oi; }
                }
                if (lane == 0) xidx[row] = bi;
            }
        }
        __syncthreads();
    }
}

// ---------------- launcher ----------------
extern "C" void kernel_launch(void* const* d_in, const int* in_sizes, int n_in,
                              void* d_out, int out_size)
{
    const float* qr    = (const float*)d_in[0];
    const float* w_in  = (const float*)d_in[1];
    const float* b_in  = (const float*)d_in[2];
    const float* w_ih  = (const float*)d_in[3];
    const float* w_hh  = (const float*)d_in[4];
    const float* b_ih  = (const float*)d_in[5];
    const float* b_hh  = (const float*)d_in[6];
    const float* w_out = (const float*)d_in[7];
    const float* b_out = (const float*)d_in[8];
    float* out = (float*)d_out;

    repack_kernel<<<512, 256>>>(w_in, w_ih, w_hh, b_ih, b_hh, w_out);

    cudaFuncSetAttribute((const void*)decoder_kernel,
                         cudaFuncAttributeMaxDynamicSharedMemorySize, SMEM_BYTES);
    decoder_kernel<<<NCTA, NTH, SMEM_BYTES>>>(qr, b_in, b_out, out);
}

// round 15
// speedup vs baseline: 1.1151x; 1.1151x over previous
#include <cuda_runtime.h>
#include <math.h>

// Problem constants (fixed shapes)
#define BW_TOTAL 8192   // B*W rows
#define HDIM     512    // hidden
#define VOCAB    128    // A
#define QDIM     256    // Q
#define CLEN     20     // max_char_len
#define MROWS    28     // rows per CTA
#define NTH      256    // 8 warps (R10 config — proven best)
#define NCTA     293    // ceil(8192/28)
#define HPAD     36     // padded row stride of transposed h (floats)

// ---------------- device scratch (repacked weights) ----------------
// Arithmetic contract (bit-exact vs reference backend): every output element
// is ONE fp32 FMA chain over k ascending from 0. f32x2 packs two ROWS per
// register in Phase A (two vocab in Phase B); each lane is its own chain.
__device__ float4 g_wpkG4[262144];   // w_hh:  [ui:16][k:512][lane:32] -> (i,f,g,o) for unit u=ui*32+lane
__device__ float4 g_wihT4[65536];    // w_ih^T gather: [a:128][u:512] -> (i,f,g,o)
__device__ float4 g_wout4[16384];    // w_out: [k:512][lane:32] -> vocab (4*lane..4*lane+3)
__device__ float4 g_win4T[32768];    // w_in:  [k4:64][u:512] -> w_in[u][4k4..4k4+3]
__device__ float4 g_bsum4[512];      // b_ih+b_hh: [u:512] -> (i,f,g,o)

__global__ void repack_kernel(const float* __restrict__ w_in,
                              const float* __restrict__ w_ih,
                              const float* __restrict__ w_hh,
                              const float* __restrict__ b_ih,
                              const float* __restrict__ b_hh,
                              const float* __restrict__ w_out)
{
    int idx = blockIdx.x * blockDim.x + threadIdx.x;
    int stride = gridDim.x * blockDim.x;
    float* wpk = (float*)g_wpkG4;
    for (int i = idx; i < 1048576; i += stride) {
        int g = i & 3, lane = (i >> 2) & 31, k = (i >> 7) & 511, ui = i >> 16;
        wpk[i] = w_hh[(g * 512 + ui * 32 + lane) * HDIM + k];
    }
    float* wih = (float*)g_wihT4;
    for (int i = idx; i < 262144; i += stride) {
        int g = i & 3, u = (i >> 2) & 511, a = i >> 11;
        wih[i] = w_ih[(g * 512 + u) * VOCAB + a];
    }
    float* wou = (float*)g_wout4;
    for (int i = idx; i < 65536; i += stride) {
        int j = i & 3, lane = (i >> 2) & 31, k = i >> 7;
        wou[i] = w_out[(4 * lane + j) * HDIM + k];
    }
    float* win = (float*)g_win4T;
    for (int i = idx; i < 131072; i += stride) {
        int j = i & 3, u = (i >> 2) & 511, k4 = i >> 11;
        win[i] = w_in[u * QDIM + 4 * k4 + j];
    }
    float* bs = (float*)g_bsum4;
    for (int i = idx; i < 2048; i += stride) {
        int g = i & 3, u = i >> 2;
        bs[i] = __fadd_rn(b_ih[g * 512 + u], b_hh[g * 512 + u]);
    }
}

// ---------------- f32x2 helpers ----------------
typedef unsigned long long ull;

__device__ __forceinline__ void dfma(ull& d, ull a, ull b) {
    asm("fma.rn.f32x2 %0, %1, %2, %0;" : "+l"(d) : "l"(a), "l"(b));
}
__device__ __forceinline__ ull f2u(float x, float y) {
    ull r; asm("mov.b64 %0, {%1, %2};" : "=l"(r) : "f"(x), "f"(y)); return r;
}
__device__ __forceinline__ float2 u2f(ull v) {
    float2 r; asm("mov.b64 {%0, %1}, %2;" : "=f"(r.x), "=f"(r.y) : "l"(v)); return r;
}

// ---------------- XLA elemental tanh / logistic (no contraction) ----------------
__device__ __forceinline__ float fast_tanh(float x) {
    const float kClamp = 7.90531110763549805f;
    float xc = fminf(fmaxf(x, -kClamp), kClamp);
    float x2 = __fmul_rn(xc, xc);
    float p = -2.76076847742355e-16f;
    p = __fadd_rn(__fmul_rn(p, x2), 2.00018790482477e-13f);
    p = __fadd_rn(__fmul_rn(p, x2), -8.60467152213735e-11f);
    p = __fadd_rn(__fmul_rn(p, x2), 5.12229709037114e-08f);
    p = __fadd_rn(__fmul_rn(p, x2), 1.48572235717979e-05f);
    p = __fadd_rn(__fmul_rn(p, x2), 6.37261928875436e-04f);
    p = __fadd_rn(__fmul_rn(p, x2), 4.89352455891786e-03f);
    float np = __fmul_rn(xc, p);
    float q = 1.19825839466702e-06f;
    q = __fadd_rn(__fmul_rn(q, x2), 1.18534705686654e-04f);
    q = __fadd_rn(__fmul_rn(q, x2), 2.26843463243900e-03f);
    q = __fadd_rn(__fmul_rn(q, x2), 4.89352518554385e-03f);
    float r = __fdiv_rn(np, q);
    return (fabsf(x) < 0.0004f) ? x : r;
}
__device__ __forceinline__ float sig_x(float x) {
    float t = fast_tanh(__fmul_rn(0.5f, x));
    return __fadd_rn(__fmul_rn(0.5f, t), 0.5f);
}

// ---------------- persistent decoder kernel ----------------
// smem: transposed h ping-pong hT[2][512][HPAD], c [28][512], xidx[28]
#define SMEM_FLOATS (2 * HDIM * HPAD + MROWS * HDIM + 32)
#define SMEM_BYTES  (SMEM_FLOATS * 4)

__global__ void __launch_bounds__(NTH, 1)
decoder_kernel(const float* __restrict__ qr,
               const float* __restrict__ b_in,
               const float* __restrict__ b_out,
               float* __restrict__ out)
{
    extern __shared__ float sm[];
    float* hT0  = sm;                          // [k:512][HPAD]
    float* hT1  = sm + HDIM * HPAD;            // [k:512][HPAD]
    float* cs   = sm + 2 * HDIM * HPAD;        // [row:28][u:512]
    int*   xidx = (int*)(sm + 2 * HDIM * HPAD + MROWS * HDIM);

    const int tid  = threadIdx.x;
    const int lane = tid & 31;
    const int wid  = tid >> 5;                 // 0..7
    const int growbase = blockIdx.x * MROWS;

    // ===== Phase 0a: stage X transposed into cs region: xsT[k:256][HPAD] =====
    float* xsT = cs;
    for (int i = tid; i < MROWS * QDIM; i += NTH) {
        int row = i >> 8, q = i & 255;
        int gr = growbase + row;
        float v = 0.0f;
        if (gr < BW_TOTAL) v = __ldg(qr + (size_t)gr * QDIM + q);
        xsT[q * HPAD + row] = v;
    }
    if (tid < MROWS) xidx[tid] = 0;            // <start>
    __syncthreads();

    // ===== Phase 0b: h0 = X @ w_in^T + b_in (8 warps x 2 passes, all 28 rows) =====
    for (int pass = 0; pass < 2; ++pass) {
        const int ui = 2 * wid + pass;
        const int u  = ui * 32 + lane;
        ull acc[14];
#pragma unroll
        for (int rp = 0; rp < 14; ++rp) acc[rp] = 0ull;
        const float4* wip = g_win4T + u;
#pragma unroll 1
        for (int k4 = 0; k4 < 64; ++k4) {
            float4 w = __ldg(wip + k4 * 512);
#define XSTEP(WS, KO)                                                          \
            {                                                                  \
                ull b_ = f2u(WS, WS);                                          \
                const float4* xr = (const float4*)(xsT + (4 * k4 + (KO)) * HPAD); \
                _Pragma("unroll")                                              \
                for (int rq = 0; rq < 7; ++rq) {                               \
                    float4 xv = xr[rq];                                        \
                    dfma(acc[2 * rq],     f2u(xv.x, xv.y), b_);                \
                    dfma(acc[2 * rq + 1], f2u(xv.z, xv.w), b_);                \
                }                                                              \
            }
            XSTEP(w.x, 0) XSTEP(w.y, 1) XSTEP(w.z, 2) XSTEP(w.w, 3)
#undef XSTEP
        }
        float bi = __ldg(b_in + u);
#pragma unroll
        for (int rp = 0; rp < 14; ++rp) {
            float2 v = u2f(acc[rp]);
            hT0[u * HPAD + 2 * rp]     = __fadd_rn(v.x, bi);
            hT0[u * HPAD + 2 * rp + 1] = __fadd_rn(v.y, bi);
        }
    }
    __syncthreads();
    // zero c (xsT region now dead)
    for (int i = tid; i < MROWS * HDIM; i += NTH) cs[i] = 0.0f;
    __syncthreads();

    float4 bo4 = __ldg(((const float4*)b_out) + lane);   // vocab 4*lane..4*lane+3

    // ===== main recurrence: 20 steps =====
    for (int t = 0; t < CLEN; ++t) {
        const float* hold = (t & 1) ? hT1 : hT0;
        float*       hnew = (t & 1) ? hT0 : hT1;

        // ---- Phase A: unit-partitioned, weight-stationary gate-major ordering ----
        // Per k-offset: load all 14 h row-pairs first, then for each gate keep the
        // duplicated weight pair in the SAME operand slot across 14 consecutive
        // FFMA2s (operand-reuse experiment). Chain order per (row,unit,gate) is
        // unchanged: k ascending 0..511 -> bit-exact vs R10.
        for (int pass = 0; pass < 2; ++pass) {
            const int ui = 2 * wid + pass;
            const int u  = ui * 32 + lane;
            ull acc[14][4];
#pragma unroll
            for (int rp = 0; rp < 14; ++rp)
#pragma unroll
                for (int g = 0; g < 4; ++g) acc[rp][g] = 0ull;

            const float4* wp = g_wpkG4 + (size_t)ui * 512 * 32 + lane;
            // prefetch iter 0 weights
            float4 w0 = __ldg(wp), w1 = __ldg(wp + 32),
                   w2 = __ldg(wp + 64), w3 = __ldg(wp + 96);

#pragma unroll 1
            for (int k4 = 0; k4 < 128; ++k4) {
                int kn = (k4 < 127) ? k4 + 1 : 127;
                const float4* wn = wp + kn * 128;
                float4 n0 = __ldg(wn), n1 = __ldg(wn + 32),
                       n2 = __ldg(wn + 64), n3 = __ldg(wn + 96);
                const float* hk = hold + (4 * k4) * HPAD;

#define KSTEP(W, KO)                                                           \
                {                                                              \
                    const float4* hr = (const float4*)(hk + (KO) * HPAD);      \
                    float4 hv0 = hr[0], hv1 = hr[1], hv2 = hr[2], hv3 = hr[3], \
                           hv4 = hr[4], hv5 = hr[5], hv6 = hr[6];              \
                    ull ha0 = f2u(hv0.x, hv0.y), hb0 = f2u(hv0.z, hv0.w);      \
                    ull ha1 = f2u(hv1.x, hv1.y), hb1 = f2u(hv1.z, hv1.w);      \
                    ull ha2 = f2u(hv2.x, hv2.y), hb2 = f2u(hv2.z, hv2.w);      \
                    ull ha3 = f2u(hv3.x, hv3.y), hb3 = f2u(hv3.z, hv3.w);      \
                    ull ha4 = f2u(hv4.x, hv4.y), hb4 = f2u(hv4.z, hv4.w);      \
                    ull ha5 = f2u(hv5.x, hv5.y), hb5 = f2u(hv5.z, hv5.w);      \
                    ull ha6 = f2u(hv6.x, hv6.y), hb6 = f2u(hv6.z, hv6.w);      \
                    {                                                          \
                        ull wg = f2u(W.x, W.x);                                \
                        dfma(acc[0][0],  ha0, wg); dfma(acc[1][0],  hb0, wg);  \
                        dfma(acc[2][0],  ha1, wg); dfma(acc[3][0],  hb1, wg);  \
                        dfma(acc[4][0],  ha2, wg); dfma(acc[5][0],  hb2, wg);  \
                        dfma(acc[6][0],  ha3, wg); dfma(acc[7][0],  hb3, wg);  \
                        dfma(acc[8][0],  ha4, wg); dfma(acc[9][0],  hb4, wg);  \
                        dfma(acc[10][0], ha5, wg); dfma(acc[11][0], hb5, wg);  \
                        dfma(acc[12][0], ha6, wg); dfma(acc[13][0], hb6, wg);  \
                    }                                                          \
                    {                                                          \
                        ull wg = f2u(W.y, W.y);                                \
                        dfma(acc[0][1],  ha0, wg); dfma(acc[1][1],  hb0, wg);  \
                        dfma(acc[2][1],  ha1, wg); dfma(acc[3][1],  hb1, wg);  \
                        dfma(acc[4][1],  ha2, wg); dfma(acc[5][1],  hb2, wg);  \
                        dfma(acc[6][1],  ha3, wg); dfma(acc[7][1],  hb3, wg);  \
                        dfma(acc[8][1],  ha4, wg); dfma(acc[9][1],  hb4, wg);  \
                        dfma(acc[10][1], ha5, wg); dfma(acc[11][1], hb5, wg);  \
                        dfma(acc[12][1], ha6, wg); dfma(acc[13][1], hb6, wg);  \
                    }                                                          \
                    {                                                          \
                        ull wg = f2u(W.z, W.z);                                \
                        dfma(acc[0][2],  ha0, wg); dfma(acc[1][2],  hb0, wg);  \
                        dfma(acc[2][2],  ha1, wg); dfma(acc[3][2],  hb1, wg);  \
                        dfma(acc[4][2],  ha2, wg); dfma(acc[5][2],  hb2, wg);  \
                        dfma(acc[6][2],  ha3, wg); dfma(acc[7][2],  hb3, wg);  \
                        dfma(acc[8][2],  ha4, wg); dfma(acc[9][2],  hb4, wg);  \
                        dfma(acc[10][2], ha5, wg); dfma(acc[11][2], hb5, wg);  \
                        dfma(acc[12][2], ha6, wg); dfma(acc[13][2], hb6, wg);  \
                    }                                                          \
                    {                                                          \
                        ull wg = f2u(W.w, W.w);                                \
                        dfma(acc[0][3],  ha0, wg); dfma(acc[1][3],  hb0, wg);  \
                        dfma(acc[2][3],  ha1, wg); dfma(acc[3][3],  hb1, wg);  \
                        dfma(acc[4][3],  ha2, wg); dfma(acc[5][3],  hb2, wg);  \
                        dfma(acc[6][3],  ha3, wg); dfma(acc[7][3],  hb3, wg);  \
                        dfma(acc[8][3],  ha4, wg); dfma(acc[9][3],  hb4, wg);  \
                        dfma(acc[10][3], ha5, wg); dfma(acc[11][3], hb5, wg);  \
                        dfma(acc[12][3], ha6, wg); dfma(acc[13][3], hb6, wg);  \
                    }                                                          \
                }
                KSTEP(w0, 0) KSTEP(w1, 1) KSTEP(w2, 2) KSTEP(w3, 3)
#undef KSTEP
                w0 = n0; w1 = n1; w2 = n2; w3 = n3;
            }

            // pointwise epilogue for this unit column (28 rows)
            float4 bs = g_bsum4[u];
#pragma unroll
            for (int rp = 0; rp < 14; ++rp) {
                float2 vi = u2f(acc[rp][0]);
                float2 vf = u2f(acc[rp][1]);
                float2 vg = u2f(acc[rp][2]);
                float2 vo = u2f(acc[rp][3]);
#pragma unroll
                for (int e = 0; e < 2; ++e) {
                    int row = 2 * rp + e;
                    float di = e ? vi.y : vi.x;
                    float df = e ? vf.y : vf.x;
                    float dg = e ? vg.y : vg.x;
                    float dd = e ? vo.y : vo.x;
                    float4 wv = g_wihT4[(size_t)xidx[row] * HDIM + u];
                    // reference order: (x-proj + h-proj) + bias
                    float gi = __fadd_rn(__fadd_rn(wv.x, di), bs.x);
                    float gf = __fadd_rn(__fadd_rn(wv.y, df), bs.y);
                    float gg = __fadd_rn(__fadd_rn(wv.z, dg), bs.z);
                    float go = __fadd_rn(__fadd_rn(wv.w, dd), bs.w);
                    float iv = sig_x(gi);
                    float fv = sig_x(gf);
                    float gv = fast_tanh(gg);
                    float ov = sig_x(go);
                    float cv = __fadd_rn(__fmul_rn(fv, cs[row * HDIM + u]),
                                         __fmul_rn(iv, gv));
                    cs[row * HDIM + u] = cv;
                    hnew[u * HPAD + row] = __fmul_rn(ov, fast_tanh(cv));
                }
            }
        }
        __syncthreads();

        // ---- Phase B: logits = h_new @ w_out^T + b_out ; store ; argmax ----
        if (wid < 7) {
            ull a01[4] = {0,0,0,0}, a23[4] = {0,0,0,0};
            const float4* wq = g_wout4 + lane;
#pragma unroll 1
            for (int u4 = 0; u4 < 128; ++u4) {
                float4 w0 = __ldg(wq + (4 * u4 + 0) * 32);
                float4 w1 = __ldg(wq + (4 * u4 + 1) * 32);
                float4 w2 = __ldg(wq + (4 * u4 + 2) * 32);
                float4 w3 = __ldg(wq + (4 * u4 + 3) * 32);
#define USTEP(W, UO)                                                           \
                {                                                              \
                    float4 hv = ((const float4*)(hnew + (4*u4+(UO))*HPAD))[wid]; \
                    ull wab = f2u(W.x, W.y), wcd = f2u(W.z, W.w);              \
                    dfma(a01[0], f2u(hv.x, hv.x), wab);                        \
                    dfma(a23[0], f2u(hv.x, hv.x), wcd);                        \
                    dfma(a01[1], f2u(hv.y, hv.y), wab);                        \
                    dfma(a23[1], f2u(hv.y, hv.y), wcd);                        \
                    dfma(a01[2], f2u(hv.z, hv.z), wab);                        \
                    dfma(a23[2], f2u(hv.z, hv.z), wcd);                        \
                    dfma(a01[3], f2u(hv.w, hv.w), wab);                        \
                    dfma(a23[3], f2u(hv.w, hv.w), wcd);                        \
                }
                USTEP(w0, 0) USTEP(w1, 1) USTEP(w2, 2) USTEP(w3, 3)
#undef USTEP
            }
#pragma unroll
            for (int r = 0; r < 4; ++r) {
                int row = 4 * wid + r;
                int gr = growbase + row;
                float2 v01 = u2f(a01[r]), v23 = u2f(a23[r]);
                float lg0 = __fadd_rn(v01.x, bo4.x);
                float lg1 = __fadd_rn(v01.y, bo4.y);
                float lg2 = __fadd_rn(v23.x, bo4.z);
                float lg3 = __fadd_rn(v23.y, bo4.w);

                if (gr < BW_TOTAL) {
                    float4 o4 = make_float4(lg0, lg1, lg2, lg3);
                    *(float4*)(out + ((size_t)gr * CLEN + t) * VOCAB + 4 * lane) = o4;
                }
                // local argmax (ascending index, first-max tie-break)
                float bv = lg0; int bi = 4 * lane;
                if (lg1 > bv) { bv = lg1; bi = 4 * lane + 1; }
                if (lg2 > bv) { bv = lg2; bi = 4 * lane + 2; }
                if (lg3 > bv) { bv = lg3; bi = 4 * lane + 3; }
#pragma unroll
                for (int off = 16; off; off >>= 1) {
                    float ov = __shfl_xor_sync(0xffffffffu, bv, off);
                    int   oi = __shfl_xor_sync(0xffffffffu, bi, off);
                    if (ov > bv || (ov == bv && oi < bi)) { bv = ov; bi = oi; }
                }
                if (lane == 0) xidx[row] = bi;
            }
        }
        __syncthreads();
    }
}

// ---------------- launcher ----------------
extern "C" void kernel_launch(void* const* d_in, const int* in_sizes, int n_in,
                              void* d_out, int out_size)
{
    const float* qr    = (const float*)d_in[0];
    const float* w_in  = (const float*)d_in[1];
    const float* b_in  = (const float*)d_in[2];
    const float* w_ih  = (const float*)d_in[3];
    const float* w_hh  = (const float*)d_in[4];
    const float* b_ih  = (const float*)d_in[5];
    const float* b_hh  = (const float*)d_in[6];
    const float* w_out = (const float*)d_in[7];
    const float* b_out = (const float*)d_in[8];
    float* out = (float*)d_out;

    repack_kernel<<<512, 256>>>(w_in, w_ih, w_hh, b_ih, b_hh, w_out);

    cudaFuncSetAttribute((const void*)decoder_kernel,
                         cudaFuncAttributeMaxDynamicSharedMemorySize, SMEM_BYTES);
    decoder_kernel<<<NCTA, NTH, SMEM_BYTES>>>(qr, b_in, b_out, out);
}